// round 13
// baseline (speedup 1.0000x reference)
#include <cuda_runtime.h>
#include <cfloat>

#define BB 256
#define TT 512
#define KK 128
#define TRP 132   // padded transposed-transitions row stride (floats)

// Scratch (__device__ globals only — no runtime allocation)
__device__ float g_states[(size_t)BB * TT * KK];   // 64 MiB Viterbi states
__device__ int   g_order[BB];                      // rank -> batch

// ---------------------------------------------------------------------------
// Rank batches by descending length. CTA i handles ranks 2i and 2i+1
// (adjacent ranks => near-equal lengths => minimal predication waste).
// ---------------------------------------------------------------------------
__global__ void order_kernel(const int* __restrict__ lens)
{
    __shared__ int sl[BB];
    const int b = threadIdx.x;
    sl[b] = lens[b];
    __syncthreads();
    const int L = sl[b];
    int r = 0;
    #pragma unroll 8
    for (int i = 0; i < BB; ++i) {
        int Li = sl[i];
        r += (Li > L) || (Li == L && i < b);
    }
    g_order[r] = b;
}

// ---------------------------------------------------------------------------
// Packed f32x2 add (sm_103a). max.f32x2 does not exist; FMNMX stays scalar.
// ---------------------------------------------------------------------------
__device__ __forceinline__ unsigned long long addx2(unsigned long long a,
                                                    unsigned long long b) {
    unsigned long long r;
    asm("add.rn.f32x2 %0, %1, %2;" : "=l"(r) : "l"(a), "l"(b));
    return r;
}
__device__ __forceinline__ float2 unpk(unsigned long long v) {
    float2 r;
    asm("mov.b64 {%0, %1}, %2;" : "=f"(r.x), "=f"(r.y) : "l"(v));
    return r;
}
__device__ __forceinline__ unsigned long long pk(float lo, float hi) {
    unsigned long long r;
    asm("mov.b64 %0, {%1, %2};" : "=l"(r) : "f"(lo), "f"(hi));
    return r;
}

// ---------------------------------------------------------------------------
// Backtrace helpers (warp-uniform argmax, first-index tie-break)
// ---------------------------------------------------------------------------
__device__ __forceinline__ unsigned redux_max_u32(unsigned v) {
    unsigned r;
    asm("redux.sync.max.u32 %0, %1, 0xffffffff;" : "=r"(r) : "r"(v));
    return r;
}
__device__ __forceinline__ unsigned redux_min_u32(unsigned v) {
    unsigned r;
    asm("redux.sync.min.u32 %0, %1, 0xffffffff;" : "=r"(r) : "r"(v));
    return r;
}
__device__ __forceinline__ unsigned fkey(float f) {
    unsigned u = __float_as_uint(f);
    return u ^ ((unsigned)((int)u >> 31) | 0x80000000u);
}
__device__ __forceinline__ int argmax128(float4 v, int l)
{
    unsigned k0 = fkey(v.x), k1 = fkey(v.y), k2 = fkey(v.z), k3 = fkey(v.w);
    unsigned km = max(max(k0, k1), max(k2, k3));
    unsigned M  = redux_max_u32(km);
    unsigned il = 0xFFFFFFFFu;
    if (k3 == M) il = 4 * l + 3;
    if (k2 == M) il = 4 * l + 2;
    if (k1 == M) il = 4 * l + 1;
    if (k0 == M) il = 4 * l + 0;
    return (int)redux_min_u32(il);
}

__device__ __forceinline__ void bt_step(float4 cur, const float* __restrict__ s_tr,
                                        int& tag, float* __restrict__ outrow,
                                        int l, bool addtr)
{
    if (addtr) {
        float4 tc = *reinterpret_cast<const float4*>(&s_tr[tag * TRP + 4 * l]);
        cur.x += tc.x; cur.y += tc.y; cur.z += tc.z; cur.w += tc.w;
    }
    tag = argmax128(cur, l);
    float4 r;
    r.x = (4 * l + 0 == tag) ? 1.0f : 0.0f;
    r.y = (4 * l + 1 == tag) ? 1.0f : 0.0f;
    r.z = (4 * l + 2 == tag) ? 1.0f : 0.0f;
    r.w = (4 * l + 3 == tag) ? 1.0f : 0.0f;
    reinterpret_cast<float4*>(outrow)[l] = r;
}

// Single-batch forward step body: partial max over all 128 i for tag j.
__device__ __forceinline__ float step_body(const ulonglong2* __restrict__ sp,
                                           const unsigned long long* __restrict__ ad)
{
    float m0 = -FLT_MAX, m1 = -FLT_MAX, m2 = -FLT_MAX, m3 = -FLT_MAX;
    float m4 = -FLT_MAX, m5 = -FLT_MAX, m6 = -FLT_MAX, m7 = -FLT_MAX;
    #pragma unroll
    for (int q = 0; q < 32; q += 2) {
        ulonglong2 sa = sp[q];
        float2 u0 = unpk(addx2(sa.x, ad[2 * q + 0]));
        float2 u1 = unpk(addx2(sa.y, ad[2 * q + 1]));
        m0 = fmaxf(m0, u0.x);
        m1 = fmaxf(m1, u0.y);
        m2 = fmaxf(m2, u1.x);
        m3 = fmaxf(m3, u1.y);
        ulonglong2 sb = sp[q + 1];
        float2 u2 = unpk(addx2(sb.x, ad[2 * q + 2]));
        float2 u3 = unpk(addx2(sb.y, ad[2 * q + 3]));
        m4 = fmaxf(m4, u2.x);
        m5 = fmaxf(m5, u2.y);
        m6 = fmaxf(m6, u3.x);
        m7 = fmaxf(m7, u3.y);
    }
    return fmaxf(fmaxf(fmaxf(m0, m1), fmaxf(m2, m3)),
                 fmaxf(fmaxf(m4, m5), fmaxf(m6, m7)));
}

// ---------------------------------------------------------------------------
// Fused Viterbi: one CTA = TWO batches, processed by the SAME 128 threads in
// one interleaved instruction stream (intra-warp ILP across batches).
// Transition registers and the per-step barrier are shared between batches.
// ---------------------------------------------------------------------------
__global__ void __launch_bounds__(128, 1) crf_kernel(
    const float* __restrict__ pot,
    const float* __restrict__ trans,
    const int*   __restrict__ lens,
    float*       __restrict__ out)
{
    extern __shared__ float sm[];
    float* s_tr  = sm;                 // KK*TRP: transposed transitions
    float* s_stA = sm + KK * TRP;      // 2*KK ping-pong state, batch A
    float* s_stB = s_stA + 2 * KK;     // 2*KK ping-pong state, batch B

    const int j = threadIdx.x;
    const int bA = g_order[2 * blockIdx.x + 0];
    const int bB = g_order[2 * blockIdx.x + 1];
    const int lenA = lens[bA];
    const int lenB = lens[bB];
    const int tmax = max(lenA, lenB);
    const size_t baseA = (size_t)bA * TT * KK;
    const size_t baseB = (size_t)bB * TT * KK;

    // Shared transitions column j -> 64 packed u64 registers; also stage the
    // transposed copy in smem for the backtraces.
    unsigned long long ad[64];
    #pragma unroll
    for (int q = 0; q < 32; ++q) {
        float v0 = trans[(4 * q + 0) * KK + j];
        float v1 = trans[(4 * q + 1) * KK + j];
        float v2 = trans[(4 * q + 2) * KK + j];
        float v3 = trans[(4 * q + 3) * KK + j];
        ad[2 * q + 0] = pk(v0, v1);
        ad[2 * q + 1] = pk(v2, v3);
        *reinterpret_cast<float4*>(&s_tr[j * TRP + 4 * q]) =
            make_float4(v0, v1, v2, v3);
    }

    {
        float sA = pot[baseA + j];
        float sB = pot[baseB + j];
        s_stA[j] = sA;
        s_stB[j] = sB;
        g_states[baseA + j] = sA;
        g_states[baseB + j] = sB;
    }

    // Depth-4 prefetch rings for both batches' emissions.
    const int lm1A = lenA - 1, lm1B = lenB - 1;
    float xrA[4], xrB[4];
    #pragma unroll
    for (int d = 0; d < 4; ++d) {
        int ta = (1 + d < lm1A) ? (1 + d) : lm1A;
        int tb = (1 + d < lm1B) ? (1 + d) : lm1B;
        xrA[d] = (lenA > 1) ? pot[baseA + (size_t)ta * KK + j] : 0.0f;
        xrB[d] = (lenB > 1) ? pot[baseB + (size_t)tb * KK + j] : 0.0f;
    }
    __syncthreads();

    // ---- forward Viterbi: both batches per barrier round ----
    int p = 0;
    #pragma unroll 2
    for (int t = 1; t < tmax; ++t) {
        const bool doA = (t < lenA);
        const bool doB = (t < lenB);

        if (doA & doB) {
            float xA = xrA[(t - 1) & 3];
            float xB = xrB[(t - 1) & 3];
            int ta = (t + 4 < lm1A) ? (t + 4) : lm1A;
            int tb = (t + 4 < lm1B) ? (t + 4) : lm1B;
            xrA[(t - 1) & 3] = pot[baseA + (size_t)ta * KK + j];
            xrB[(t - 1) & 3] = pot[baseB + (size_t)tb * KK + j];

            // Two independent unrolled bodies in one basic block: ptxas
            // interleaves them, filling each other's latency stalls.
            float pmA = step_body(
                reinterpret_cast<const ulonglong2*>(s_stA + p * KK), ad);
            float pmB = step_body(
                reinterpret_cast<const ulonglong2*>(s_stB + p * KK), ad);

            float nsA = xA + pmA;
            float nsB = xB + pmB;
            s_stA[(p ^ 1) * KK + j] = nsA;
            s_stB[(p ^ 1) * KK + j] = nsB;
            g_states[baseA + (size_t)t * KK + j] = nsA;
            g_states[baseB + (size_t)t * KK + j] = nsB;
        } else if (doA) {
            float xA = xrA[(t - 1) & 3];
            int ta = (t + 4 < lm1A) ? (t + 4) : lm1A;
            xrA[(t - 1) & 3] = pot[baseA + (size_t)ta * KK + j];
            float pmA = step_body(
                reinterpret_cast<const ulonglong2*>(s_stA + p * KK), ad);
            float nsA = xA + pmA;
            s_stA[(p ^ 1) * KK + j] = nsA;
            g_states[baseA + (size_t)t * KK + j] = nsA;
        } else {
            float xB = xrB[(t - 1) & 3];
            int tb = (t + 4 < lm1B) ? (t + 4) : lm1B;
            xrB[(t - 1) & 3] = pot[baseB + (size_t)tb * KK + j];
            float pmB = step_body(
                reinterpret_cast<const ulonglong2*>(s_stB + p * KK), ad);
            float nsB = xB + pmB;
            s_stB[(p ^ 1) * KK + j] = nsB;
            g_states[baseB + (size_t)t * KK + j] = nsB;
        }
        __syncthreads();
        p ^= 1;
    }

    // ---- epilogue ----
    // warp 0: backtrace A.  warp 1: backtrace B.
    // warp 2: tag-0 tail rows of A.  warp 3: tag-0 tail rows of B.
    const int w = j >> 5;
    const int l = j & 31;

    if (w >= 2) {
        const size_t base = (w == 2) ? baseA : baseB;
        const int len = (w == 2) ? lenA : lenB;
        for (int r = len; r < TT; ++r) {
            float4 v = make_float4(l == 0 ? 1.0f : 0.0f, 0.0f, 0.0f, 0.0f);
            reinterpret_cast<float4*>(out + base + (size_t)r * KK)[l] = v;
        }
        return;
    }

    const size_t base = (w == 0) ? baseA : baseB;
    const int len = (w == 0) ? lenA : lenB;

    auto LDst = [&](int t) -> float4 {
        if (t < 0) return make_float4(0.f, 0.f, 0.f, 0.f);
        return reinterpret_cast<const float4*>(&g_states[base + (size_t)t * KK])[l];
    };
    float* const ob = out + base;

    int tag = 0;
    float4 c0 = LDst(len - 1);
    int t = len - 2;
    float4 p0 = LDst(t), p1 = LDst(t - 1), p2 = LDst(t - 2), p3 = LDst(t - 3);

    bt_step(c0, s_tr, tag, ob + (size_t)(len - 1) * KK, l, false);

    while (t >= 3) {
        bt_step(p0, s_tr, tag, ob + (size_t)(t    ) * KK, l, true);  p0 = LDst(t - 4);
        bt_step(p1, s_tr, tag, ob + (size_t)(t - 1) * KK, l, true);  p1 = LDst(t - 5);
        bt_step(p2, s_tr, tag, ob + (size_t)(t - 2) * KK, l, true);  p2 = LDst(t - 6);
        bt_step(p3, s_tr, tag, ob + (size_t)(t - 3) * KK, l, true);  p3 = LDst(t - 7);
        t -= 4;
    }
    if (t >= 0) bt_step(p0, s_tr, tag, ob + (size_t)(t    ) * KK, l, true);
    if (t >= 1) bt_step(p1, s_tr, tag, ob + (size_t)(t - 1) * KK, l, true);
    if (t >= 2) bt_step(p2, s_tr, tag, ob + (size_t)(t - 2) * KK, l, true);
}

// ---------------------------------------------------------------------------
extern "C" void kernel_launch(void* const* d_in, const int* in_sizes, int n_in,
                              void* d_out, int out_size)
{
    const float* pot   = (const float*)d_in[0];   // (B,T,K) f32
    const float* trans = (const float*)d_in[1];   // (K,K)   f32
    const int*   lens  = (const int*)  d_in[2];   // (B,)    i32
    float* out = (float*)d_out;                   // (B,T,K) f32

    const int smem = (KK * TRP + 4 * KK) * (int)sizeof(float);   // 69,632 B
    cudaFuncSetAttribute(crf_kernel, cudaFuncAttributeMaxDynamicSharedMemorySize, smem);

    order_kernel<<<1, BB>>>(lens);
    crf_kernel<<<BB / 2, 128, smem>>>(pot, trans, lens, out);
}